// round 1
// baseline (speedup 1.0000x reference)
#include <cuda_runtime.h>

#define NB 16
#define NL 1024
#define NDIN 512
#define NH 8
#define MROWS (NB*NL)   // 16384

// ---------------- scratch (device globals: no allocation allowed) ----------------
__device__ float g_mu[3][MROWS];
__device__ float g_rstd[3][MROWS];
__device__ float g_Q[NB*NH*NL*64];      // [b,h,l,d]  32MB
__device__ float g_K[NB*NH*NL*64];
__device__ float g_V[NB*NH*NL*64];
__device__ float g_att[MROWS*NDIN];     // attention output, [b*l, h*64+d] 32MB

// ---------------- LayerNorm row statistics ----------------
__global__ __launch_bounds__(256) void ln_stats_kernel(
    const float* __restrict__ q, const float* __restrict__ k, const float* __restrict__ v)
{
    int warp = threadIdx.x >> 5, lane = threadIdx.x & 31;
    int row = blockIdx.x * 8 + warp;
    int t = blockIdx.y;
    const float* x = (t == 0 ? q : (t == 1 ? k : v)) + (size_t)row * NDIN;
    const float4* x4 = (const float4*)x;
    float s = 0.f, ss = 0.f;
    #pragma unroll
    for (int i = 0; i < 4; i++) {
        float4 a = x4[lane + 32 * i];
        s  += a.x + a.y + a.z + a.w;
        ss += a.x*a.x + a.y*a.y + a.z*a.z + a.w*a.w;
    }
    #pragma unroll
    for (int o = 16; o; o >>= 1) {
        s  += __shfl_xor_sync(0xffffffffu, s, o);
        ss += __shfl_xor_sync(0xffffffffu, ss, o);
    }
    if (lane == 0) {
        float mu = s * (1.f / 512.f);
        float var = ss * (1.f / 512.f) - mu * mu;
        g_mu[t][row] = mu;
        g_rstd[t][row] = rsqrtf(var + 1e-5f);
    }
}

// ---------------- projection GEMM: C = LN(x) @ W^T, writes [b,h,l,d] ----------------
// M=16384, N=512, K=512.  BM=BN=128, BK=16, 256 threads, 8x8 micro-tile.
__global__ __launch_bounds__(256, 2) void gemm_proj_kernel(
    const float* __restrict__ q, const float* __restrict__ k, const float* __restrict__ v,
    const float* __restrict__ Wq, const float* __restrict__ Wk, const float* __restrict__ Wv,
    const float* __restrict__ g1, const float* __restrict__ b1,
    const float* __restrict__ g2, const float* __restrict__ b2,
    const float* __restrict__ g3, const float* __restrict__ b3)
{
    int t = blockIdx.z;
    const float* A     = (t == 0) ? q  : (t == 1) ? k  : v;
    const float* W     = (t == 0) ? Wq : (t == 1) ? Wk : Wv;
    const float* gamma = (t == 0) ? g1 : (t == 1) ? g2 : g3;
    const float* beta  = (t == 0) ? b1 : (t == 1) ? b2 : b3;
    float* outp        = (t == 0) ? g_Q : (t == 1) ? g_K : g_V;

    __shared__ float As[16][128];
    __shared__ float Bs[16][128];
    __shared__ float sG[512], sB[512];

    int tid = threadIdx.x;
    int mr0 = blockIdx.y * 128;
    int nr0 = blockIdx.x * 128;

    for (int i = tid; i < 512; i += 256) { sG[i] = gamma[i]; sB[i] = beta[i]; }

    int mA = tid >> 2;            // 0..63
    int kq = (tid & 3) << 2;      // 0,4,8,12
    float mu0 = g_mu[t][mr0 + mA],      rs0 = g_rstd[t][mr0 + mA];
    float mu1 = g_mu[t][mr0 + mA + 64], rs1 = g_rstd[t][mr0 + mA + 64];

    int tr = tid >> 4, tc = tid & 15;
    float acc[8][8] = {};

    __syncthreads();  // sG/sB ready

    for (int kb = 0; kb < 512; kb += 16) {
        float4 x0 = *(const float4*)&A[(size_t)(mr0 + mA) * 512 + kb + kq];
        float4 x1 = *(const float4*)&A[(size_t)(mr0 + mA + 64) * 512 + kb + kq];
        float4 gv = *(const float4*)&sG[kb + kq];
        float4 bv = *(const float4*)&sB[kb + kq];
        x0.x = ((x0.x - mu0) * rs0) * gv.x + bv.x;
        x0.y = ((x0.y - mu0) * rs0) * gv.y + bv.y;
        x0.z = ((x0.z - mu0) * rs0) * gv.z + bv.z;
        x0.w = ((x0.w - mu0) * rs0) * gv.w + bv.w;
        x1.x = ((x1.x - mu1) * rs1) * gv.x + bv.x;
        x1.y = ((x1.y - mu1) * rs1) * gv.y + bv.y;
        x1.z = ((x1.z - mu1) * rs1) * gv.z + bv.z;
        x1.w = ((x1.w - mu1) * rs1) * gv.w + bv.w;
        As[kq + 0][mA] = x0.x; As[kq + 1][mA] = x0.y; As[kq + 2][mA] = x0.z; As[kq + 3][mA] = x0.w;
        As[kq + 0][mA + 64] = x1.x; As[kq + 1][mA + 64] = x1.y; As[kq + 2][mA + 64] = x1.z; As[kq + 3][mA + 64] = x1.w;

        float4 w0 = *(const float4*)&W[(size_t)(nr0 + mA) * 512 + kb + kq];
        float4 w1 = *(const float4*)&W[(size_t)(nr0 + mA + 64) * 512 + kb + kq];
        Bs[kq + 0][mA] = w0.x; Bs[kq + 1][mA] = w0.y; Bs[kq + 2][mA] = w0.z; Bs[kq + 3][mA] = w0.w;
        Bs[kq + 0][mA + 64] = w1.x; Bs[kq + 1][mA + 64] = w1.y; Bs[kq + 2][mA + 64] = w1.z; Bs[kq + 3][mA + 64] = w1.w;
        __syncthreads();

        #pragma unroll
        for (int kk = 0; kk < 16; kk++) {
            float4 a0 = *(const float4*)&As[kk][tr * 8];
            float4 a1 = *(const float4*)&As[kk][tr * 8 + 4];
            float4 c0 = *(const float4*)&Bs[kk][tc * 8];
            float4 c1 = *(const float4*)&Bs[kk][tc * 8 + 4];
            float aa[8] = {a0.x, a0.y, a0.z, a0.w, a1.x, a1.y, a1.z, a1.w};
            float bb[8] = {c0.x, c0.y, c0.z, c0.w, c1.x, c1.y, c1.z, c1.w};
            #pragma unroll
            for (int i = 0; i < 8; i++)
                #pragma unroll
                for (int j = 0; j < 8; j++)
                    acc[i][j] += aa[i] * bb[j];
        }
        __syncthreads();
    }

    int n0 = nr0 + tc * 8;
    int h = n0 >> 6, d = n0 & 63;
    #pragma unroll
    for (int i = 0; i < 8; i++) {
        int mr = mr0 + tr * 8 + i;
        int bb = mr >> 10, l = mr & 1023;
        float* p = outp + ((size_t)(bb * NH + h) << 16) + l * 64 + d;
        *(float4*)p       = make_float4(acc[i][0], acc[i][1], acc[i][2], acc[i][3]);
        *(float4*)(p + 4) = make_float4(acc[i][4], acc[i][5], acc[i][6], acc[i][7]);
    }
}

// ---------------- fc GEMM: dynamic = g_att @ Wfc^T ----------------
__global__ __launch_bounds__(256, 2) void gemm_fc_kernel(
    const float* __restrict__ Wfc, float* __restrict__ dyn)
{
    __shared__ float As[16][128];
    __shared__ float Bs[16][128];

    int tid = threadIdx.x;
    int mr0 = blockIdx.y * 128;
    int nr0 = blockIdx.x * 128;
    int mA = tid >> 2;
    int kq = (tid & 3) << 2;
    int tr = tid >> 4, tc = tid & 15;
    float acc[8][8] = {};
    const float* A = g_att;

    for (int kb = 0; kb < 512; kb += 16) {
        float4 x0 = *(const float4*)&A[(size_t)(mr0 + mA) * 512 + kb + kq];
        float4 x1 = *(const float4*)&A[(size_t)(mr0 + mA + 64) * 512 + kb + kq];
        As[kq + 0][mA] = x0.x; As[kq + 1][mA] = x0.y; As[kq + 2][mA] = x0.z; As[kq + 3][mA] = x0.w;
        As[kq + 0][mA + 64] = x1.x; As[kq + 1][mA + 64] = x1.y; As[kq + 2][mA + 64] = x1.z; As[kq + 3][mA + 64] = x1.w;
        float4 w0 = *(const float4*)&Wfc[(size_t)(nr0 + mA) * 512 + kb + kq];
        float4 w1 = *(const float4*)&Wfc[(size_t)(nr0 + mA + 64) * 512 + kb + kq];
        Bs[kq + 0][mA] = w0.x; Bs[kq + 1][mA] = w0.y; Bs[kq + 2][mA] = w0.z; Bs[kq + 3][mA] = w0.w;
        Bs[kq + 0][mA + 64] = w1.x; Bs[kq + 1][mA + 64] = w1.y; Bs[kq + 2][mA + 64] = w1.z; Bs[kq + 3][mA + 64] = w1.w;
        __syncthreads();
        #pragma unroll
        for (int kk = 0; kk < 16; kk++) {
            float4 a0 = *(const float4*)&As[kk][tr * 8];
            float4 a1 = *(const float4*)&As[kk][tr * 8 + 4];
            float4 c0 = *(const float4*)&Bs[kk][tc * 8];
            float4 c1 = *(const float4*)&Bs[kk][tc * 8 + 4];
            float aa[8] = {a0.x, a0.y, a0.z, a0.w, a1.x, a1.y, a1.z, a1.w};
            float bb[8] = {c0.x, c0.y, c0.z, c0.w, c1.x, c1.y, c1.z, c1.w};
            #pragma unroll
            for (int i = 0; i < 8; i++)
                #pragma unroll
                for (int j = 0; j < 8; j++)
                    acc[i][j] += aa[i] * bb[j];
        }
        __syncthreads();
    }

    #pragma unroll
    for (int i = 0; i < 8; i++) {
        float* p = dyn + (size_t)(mr0 + tr * 8 + i) * 512 + nr0 + tc * 8;
        *(float4*)p       = make_float4(acc[i][0], acc[i][1], acc[i][2], acc[i][3]);
        *(float4*)(p + 4) = make_float4(acc[i][4], acc[i][5], acc[i][6], acc[i][7]);
    }
}

// ---------------- fused attention: scores + masked softmax + attn write + PV ----------------
// grid (32 qblocks, 8 heads, 16 batch), 256 threads, 1 CTA handles 32 q-rows.
__global__ __launch_bounds__(256, 1) void attn_kernel(
    const int* __restrict__ mask, float* __restrict__ attn_out)
{
    extern __shared__ float sm[];
    float* Ssc = sm;                    // [32][1024]
    float* Qt  = sm + 32 * 1024;        // [64][40]  (d-major Q tile)
    float* KVt = Qt + 64 * 40;          // [64][68]  (K: d-major; V: k-major)

    int tid = threadIdx.x;
    int q0 = blockIdx.x * 32;
    int h = blockIdx.y, b = blockIdx.z;
    size_t bh = (size_t)(b * NH + h);
    const float* Qg = g_Q + (bh << 16) + (size_t)q0 * 64;
    const float* Kg = g_K + (bh << 16);
    const float* Vg = g_V + (bh << 16);

    // load Q tile transposed: Qt[d][r]
    {
        int r = tid >> 3;
        int dq = (tid & 7) * 8;
        float4 v0 = *(const float4*)&Qg[r * 64 + dq];
        float4 v1 = *(const float4*)&Qg[r * 64 + dq + 4];
        Qt[(dq + 0) * 40 + r] = v0.x; Qt[(dq + 1) * 40 + r] = v0.y;
        Qt[(dq + 2) * 40 + r] = v0.z; Qt[(dq + 3) * 40 + r] = v0.w;
        Qt[(dq + 4) * 40 + r] = v1.x; Qt[(dq + 5) * 40 + r] = v1.y;
        Qt[(dq + 6) * 40 + r] = v1.z; Qt[(dq + 7) * 40 + r] = v1.w;
    }

    int cp = tid & 31, rq = tid >> 5;
    int c0 = cp * 2;

    // ---- pass 1: S = Q K^T / 8 into Ssc ----
    for (int kt = 0; kt < 16; kt++) {
        __syncthreads();
        {
            int c = tid >> 2, f = tid & 3;
            const float* src = &Kg[(kt * 64 + c) * 64];
            #pragma unroll
            for (int jj = 0; jj < 4; jj++) {
                int d0 = f * 16 + jj * 4;
                float4 kv = *(const float4*)&src[d0];
                KVt[(d0 + 0) * 68 + c] = kv.x;
                KVt[(d0 + 1) * 68 + c] = kv.y;
                KVt[(d0 + 2) * 68 + c] = kv.z;
                KVt[(d0 + 3) * 68 + c] = kv.w;
            }
        }
        __syncthreads();
        float a00 = 0, a01 = 0, a10 = 0, a11 = 0, a20 = 0, a21 = 0, a30 = 0, a31 = 0;
        #pragma unroll
        for (int d = 0; d < 64; d++) {
            float2 kv = *(const float2*)&KVt[d * 68 + c0];
            float4 qv = *(const float4*)&Qt[d * 40 + rq * 4];
            a00 += qv.x * kv.x; a01 += qv.x * kv.y;
            a10 += qv.y * kv.x; a11 += qv.y * kv.y;
            a20 += qv.z * kv.x; a21 += qv.z * kv.y;
            a30 += qv.w * kv.x; a31 += qv.w * kv.y;
        }
        const float sc = 0.125f;
        int col = kt * 64 + c0;
        *(float2*)&Ssc[(rq * 4 + 0) * 1024 + col] = make_float2(a00 * sc, a01 * sc);
        *(float2*)&Ssc[(rq * 4 + 1) * 1024 + col] = make_float2(a10 * sc, a11 * sc);
        *(float2*)&Ssc[(rq * 4 + 2) * 1024 + col] = make_float2(a20 * sc, a21 * sc);
        *(float2*)&Ssc[(rq * 4 + 3) * 1024 + col] = make_float2(a30 * sc, a31 * sc);
    }
    __syncthreads();

    // ---- masked softmax (exact reference algebra) + attn write ----
    {
        int warp = tid >> 5, lane = tid & 31;
        for (int rr = 0; rr < 4; rr++) {
            int r = warp * 4 + rr;
            int qg = q0 + r;
            const int* mrow = mask + ((size_t)b * 1024 + qg) * 1024;
            float* srow = &Ssc[r * 1024];
            float mx = 0.f; int cnt = 0;   // masked entries have t=0, so true max >= 0
            for (int kk = lane; kk < 1024; kk += 32) {
                float s = srow[kk];
                int mk = mrow[kk];
                bool allowed = (kk != qg) && (mk == 0);
                float tt = allowed ? s : 0.f;
                srow[kk] = tt;
                cnt += allowed ? 0 : 1;
                mx = fmaxf(mx, tt);
            }
            #pragma unroll
            for (int o = 16; o; o >>= 1) {
                mx = fmaxf(mx, __shfl_xor_sync(0xffffffffu, mx, o));
                cnt += __shfl_xor_sync(0xffffffffu, cnt, o);
            }
            float sum = 0.f;
            for (int kk = lane; kk < 1024; kk += 32) {
                float tt = srow[kk];
                float e = (tt != 0.f) ? __expf(tt - mx) : 0.f;
                srow[kk] = e;
                sum += e;
            }
            #pragma unroll
            for (int o = 16; o; o >>= 1) sum += __shfl_xor_sync(0xffffffffu, sum, o);
            float Z = sum + (float)cnt * __expf(-mx);     // full softmax denominator
            float inv = 1.f / (sum + 1e-13f * Z);
            float* orow = attn_out + (((size_t)h * NB + b) * 1024 + qg) * 1024;
            for (int kk = lane; kk < 1024; kk += 32) {
                float a = srow[kk] * inv;
                srow[kk] = a;
                orow[kk] = a;
            }
        }
    }

    // ---- pass 2: out = attn @ V ----
    int dv0 = c0;
    float o00 = 0, o01 = 0, o10 = 0, o11 = 0, o20 = 0, o21 = 0, o30 = 0, o31 = 0;
    for (int kt = 0; kt < 16; kt++) {
        __syncthreads();
        {
            int kk = tid >> 2, f = tid & 3;
            const float* src = &Vg[(kt * 64 + kk) * 64];
            #pragma unroll
            for (int jj = 0; jj < 4; jj++) {
                int d0 = f * 16 + jj * 4;
                *(float4*)&KVt[kk * 68 + d0] = *(const float4*)&src[d0];
            }
        }
        __syncthreads();
        const float* s0 = &Ssc[(rq * 4 + 0) * 1024 + kt * 64];
        const float* s1 = s0 + 1024;
        const float* s2 = s1 + 1024;
        const float* s3 = s2 + 1024;
        #pragma unroll
        for (int kk = 0; kk < 64; kk += 4) {
            float4 a0 = *(const float4*)&s0[kk];
            float4 a1 = *(const float4*)&s1[kk];
            float4 a2 = *(const float4*)&s2[kk];
            float4 a3 = *(const float4*)&s3[kk];
            float2 v0 = *(const float2*)&KVt[(kk + 0) * 68 + dv0];
            float2 v1 = *(const float2*)&KVt[(kk + 1) * 68 + dv0];
            float2 v2 = *(const float2*)&KVt[(kk + 2) * 68 + dv0];
            float2 v3 = *(const float2*)&KVt[(kk + 3) * 68 + dv0];
            o00 += a0.x * v0.x; o01 += a0.x * v0.y;
            o10 += a1.x * v0.x; o11 += a1.x * v0.y;
            o20 += a2.x * v0.x; o21 += a2.x * v0.y;
            o30 += a3.x * v0.x; o31 += a3.x * v0.y;
            o00 += a0.y * v1.x; o01 += a0.y * v1.y;
            o10 += a1.y * v1.x; o11 += a1.y * v1.y;
            o20 += a2.y * v1.x; o21 += a2.y * v1.y;
            o30 += a3.y * v1.x; o31 += a3.y * v1.y;
            o00 += a0.z * v2.x; o01 += a0.z * v2.y;
            o10 += a1.z * v2.x; o11 += a1.z * v2.y;
            o20 += a2.z * v2.x; o21 += a2.z * v2.y;
            o30 += a3.z * v2.x; o31 += a3.z * v2.y;
            o00 += a0.w * v3.x; o01 += a0.w * v3.y;
            o10 += a1.w * v3.x; o11 += a1.w * v3.y;
            o20 += a2.w * v3.x; o21 += a2.w * v3.y;
            o30 += a3.w * v3.x; o31 += a3.w * v3.y;
        }
    }
    {
        size_t base = ((size_t)b * 1024 + q0 + rq * 4) * 512 + h * 64 + dv0;
        *(float2*)&g_att[base          ] = make_float2(o00, o01);
        *(float2*)&g_att[base + 512    ] = make_float2(o10, o11);
        *(float2*)&g_att[base + 1024   ] = make_float2(o20, o21);
        *(float2*)&g_att[base + 1536   ] = make_float2(o30, o31);
    }
}

// ---------------- launch ----------------
extern "C" void kernel_launch(void* const* d_in, const int* in_sizes, int n_in,
                              void* d_out, int out_size)
{
    (void)in_sizes; (void)n_in; (void)out_size;
    const float* q   = (const float*)d_in[0];
    const float* k   = (const float*)d_in[1];
    const float* v   = (const float*)d_in[2];
    const int*   msk = (const int*)d_in[3];
    const float* Wq  = (const float*)d_in[4];
    const float* Wk  = (const float*)d_in[5];
    const float* Wv  = (const float*)d_in[6];
    const float* Wfc = (const float*)d_in[7];
    const float* g1  = (const float*)d_in[8];
    const float* b1  = (const float*)d_in[9];
    const float* g2  = (const float*)d_in[10];
    const float* b2  = (const float*)d_in[11];
    const float* g3  = (const float*)d_in[12];
    const float* b3  = (const float*)d_in[13];

    float* out = (float*)d_out;
    float* dyn_out  = out;                            // [16,1024,512]
    float* attn_out = out + (size_t)MROWS * 512;      // [128,1024,1024]

    const int attn_smem = (32 * 1024 + 64 * 40 + 64 * 68) * 4;  // 158720 B
    cudaFuncSetAttribute(attn_kernel, cudaFuncAttributeMaxDynamicSharedMemorySize, attn_smem);

    ln_stats_kernel<<<dim3(2048, 3), 256>>>(q, k, v);
    gemm_proj_kernel<<<dim3(4, 128, 3), 256>>>(q, k, v, Wq, Wk, Wv, g1, b1, g2, b2, g3, b3);
    attn_kernel<<<dim3(32, 8, 16), 256, attn_smem>>>(msk, attn_out);
    gemm_fc_kernel<<<dim3(4, 128), 256>>>(Wfc, dyn_out);
}